// round 13
// baseline (speedup 1.0000x reference)
#include <cuda_runtime.h>
#include <cuda_fp16.h>
#include <cstdint>

// Problem constants (fixed by the dataset)
#define BB 16
#define NN 16384
#define DD 128
#define EE 65536
#define NODES (BB * NN)          // 262144
#define LN_EPS 1e-5f

// ================= scratch (__device__ globals) ================================
__device__ int g_is32;
__device__ __align__(16) int g_deg[NN];
__device__ __align__(16) int g_rowptr[NN + 1];
__device__ __align__(16) int g_cursor[NN];
__device__ int g_csr[EE];
__device__ uint4 g_xh[(size_t)NODES * 16];    // x as fp16 rows (256B each) = 64MB
__device__ uint4 g_w4[4096];                  // [128 n][256 k] fp16: Ws|Wn concat

__device__ __forceinline__ int clampN(int v) {
    return v < 0 ? 0 : (v >= NN ? NN - 1 : v);
}
__device__ __forceinline__ int edge_src(const int* e32, int e) {
    return clampN(g_is32 ? e32[e] : e32[2 * e]);
}
__device__ __forceinline__ int edge_dst(const int* e32, int e) {
    return clampN(g_is32 ? e32[EE + e] : e32[2 * EE + 2 * e]);
}
__device__ __forceinline__ uint32_t packh(float a, float b) {
    __half2 t(__float2half_rn(a), __float2half_rn(b));
    return *reinterpret_cast<uint32_t*>(&t);
}
__device__ __forceinline__ uint32_t smem_u32(const void* p) {
    uint32_t a;
    asm("{ .reg .u64 t; cvta.to.shared.u64 t, %1; cvt.u32.u64 %0, t; }" : "=r"(a) : "l"(p));
    return a;
}
#define CP_ASYNC16(sa, gp) \
    asm volatile("cp.async.cg.shared.global [%0], [%1], 16;" :: "r"(sa), "l"(gp))
#define CP_COMMIT() asm volatile("cp.async.commit_group;" ::: "memory")
#define CP_WAIT0()  asm volatile("cp.async.wait_group 0;" ::: "memory")
#define LDMATRIX_X4(r0, r1, r2, r3, a) \
    asm volatile("ldmatrix.sync.aligned.m8n8.x4.shared.b16 {%0,%1,%2,%3}, [%4];" \
                 : "=r"(r0), "=r"(r1), "=r"(r2), "=r"(r3) : "r"(a))
#define MMA16816(c, a, b) \
    asm volatile("mma.sync.aligned.m16n8k16.row.col.f32.f16.f16.f32 " \
                 "{%0,%1,%2,%3}, {%4,%5,%6,%7}, {%8,%9}, {%0,%1,%2,%3};" \
                 : "+f"((c)[0]), "+f"((c)[1]), "+f"((c)[2]), "+f"((c)[3]) \
                 : "r"((a)[0]), "r"((a)[1]), "r"((a)[2]), "r"((a)[3]), \
                   "r"((b)[0]), "r"((b)[1]))

// ================= fused init: zero degrees + dtype detect + weight convert ====
__global__ void k_init(const int* __restrict__ e32,
                       const float* __restrict__ Ws, const float* __restrict__ Wn) {
    int i = blockIdx.x * blockDim.x + threadIdx.x;
    if (i == 0) g_is32 = 0;
    if (i < NN) g_deg[i] = 0;
    if (i < EE && e32[2 * i + 1] != 0) g_is32 = 1;
    if (i < DD * DD) {
        __half* w = (__half*)g_w4;
        int n = i >> 7, k = i & 127;
        w[n * 256 + k] = __float2half_rn(Ws[i]);
        w[n * 256 + 128 + k] = __float2half_rn(Wn[i]);
    }
}

// ================= fused: degree count + x -> fp16 conversion ==================
__global__ void k_count_xh(const int* __restrict__ e32, const float* __restrict__ x) {
    size_t i = (size_t)blockIdx.x * blockDim.x + threadIdx.x;
    if (i < EE) atomicAdd(&g_deg[edge_dst(e32, (int)i)], 1);
    const float4* s = (const float4*)x + 2 * i;
    float4 a = s[0], b = s[1];
    g_xh[i] = make_uint4(packh(a.x, a.y), packh(a.z, a.w),
                         packh(b.x, b.y), packh(b.z, b.w));
}

// vectorized single-block scan: 1024 threads x 16 elems, warp shuffles
__global__ void k_scan() {
    __shared__ int wsum[32], wpre[32];
    int t = threadIdx.x, lane = t & 31, w = t >> 5;
    const int4* dg = (const int4*)g_deg;
    int loc[16];
#pragma unroll
    for (int q = 0; q < 4; q++) {
        int4 v = dg[t * 4 + q];
        loc[4 * q + 0] = v.x; loc[4 * q + 1] = v.y;
        loc[4 * q + 2] = v.z; loc[4 * q + 3] = v.w;
    }
    int s = 0;
#pragma unroll
    for (int m = 0; m < 16; m++) s += loc[m];
    int inc = s;
#pragma unroll
    for (int o = 1; o < 32; o <<= 1) {
        int u = __shfl_up_sync(0xFFFFFFFFu, inc, o);
        if (lane >= o) inc += u;
    }
    if (lane == 31) wsum[w] = inc;
    __syncthreads();
    if (w == 0) {
        int a = wsum[lane], ai = a;
#pragma unroll
        for (int o = 1; o < 32; o <<= 1) {
            int u = __shfl_up_sync(0xFFFFFFFFu, ai, o);
            if (lane >= o) ai += u;
        }
        wpre[lane] = ai - a;
    }
    __syncthreads();
    int run = wpre[w] + (inc - s);
    int rp[16];
#pragma unroll
    for (int m = 0; m < 16; m++) { rp[m] = run; run += loc[m]; }
    int4* rpo = (int4*)g_rowptr;
    int4* cu = (int4*)g_cursor;
#pragma unroll
    for (int q = 0; q < 4; q++) {
        int4 o4 = make_int4(rp[4 * q], rp[4 * q + 1], rp[4 * q + 2], rp[4 * q + 3]);
        rpo[t * 4 + q] = o4;
        cu[t * 4 + q] = o4;
    }
    if (t == 1023) g_rowptr[NN] = run;
}

__global__ void k_fill(const int* __restrict__ e32) {
    int e = blockIdx.x * blockDim.x + threadIdx.x;
    if (e < EE) {
        int d = edge_dst(e32, e);
        int pos = atomicAdd(&g_cursor[d], 1);
        if (pos >= 0 && pos < EE) g_csr[pos] = edge_src(e32, e);
    }
}

// ========== fused: gather + mma.sync GEMM + bias + LN + ReLU ===================
// CTA = 128 rows x 128 cols, 256 threads = 8 warps (warp tile 32x64, 4x2 grid).
// A = [x_fp16 | neigh-mean fp16] (128 x 256); B = [Ws|Wn] (128 n x 256 k).
// cp.async stages x/B while the gather runs; epilogue is register-direct.
#define LDAB 264                              // fp16 per row (256 + 8 pad)
#define LROW (LDAB * 2)                       // 528 bytes per row
#define ROWS 128
#define ABYTES (ROWS * LROW)                  // 67584
#define BBYTES (128 * LROW)                   // 67584
#define SM_BIAS  0
#define SM_GAMMA 512
#define SM_BETA  1024
#define SM_A     2048
#define SM_B     (SM_A + ABYTES)
#define SM_P     (SM_B + BBYTES)              // float2 part[128][2] = 2048
#define SMEM_TOTAL (SM_P + 2048)              // 139264 -> 1 CTA/SM

__global__ void __launch_bounds__(256, 1)
k_mm(const float* __restrict__ bias,
     const float* __restrict__ gamma,
     const float* __restrict__ beta,
     float* __restrict__ out) {
    extern __shared__ char smem[];
    uint32_t sb = smem_u32(smem);
    int tid = threadIdx.x;
    int wid = tid >> 5, lane = tid & 31;

    if (tid < DD) {
        ((float*)(smem + SM_BIAS))[tid] = bias[tid];
        ((float*)(smem + SM_GAMMA))[tid] = gamma[tid];
        ((float*)(smem + SM_BETA))[tid] = beta[tid];
    }

    size_t g0 = (size_t)blockIdx.x * ROWS;

    // ---- cp.async staging: x rows (A cols 0..127) + B, overlapped with gather -
#pragma unroll
    for (int i = 0; i < 8; i++) {
        int idx = tid + 256 * i;            // 0..2047 (128 rows x 16 chunks)
        int r = idx >> 4, c = idx & 15;
        CP_ASYNC16(sb + SM_A + r * LROW + c * 16, (const void*)(g_xh + (g0 + r) * 16 + c));
    }
#pragma unroll
    for (int i = 0; i < 16; i++) {
        int idx = tid + 256 * i;            // 0..4095 (128 rows x 32 chunks)
        int r = idx >> 5, c = idx & 31;
        CP_ASYNC16(sb + SM_B + r * LROW + c * 16, (const void*)(g_w4 + idx));
    }
    CP_COMMIT();

    // ---- gather neighbor mean (A cols 128..255); 2 threads per row ------------
    {
        int row = tid >> 1;                 // 0..127
        int h = tid & 1;                    // half of a row (128B)
        int b = blockIdx.x >> 7;            // 128 tiles per batch
        int n = ((blockIdx.x & 127) << 7) + row;
        int s0 = g_rowptr[n];
        int s1 = g_rowptr[n + 1];
        const uint4* xb = g_xh + (size_t)b * NN * 16 + h * 8;
        float acc[64];
#pragma unroll
        for (int i = 0; i < 64; i++) acc[i] = 0.f;
        for (int e = s0; e < s1; e++) {
            const uint4* p = xb + (size_t)g_csr[e] * 16;
#pragma unroll
            for (int i = 0; i < 8; i++) {
                uint4 u = p[i];
                float2 p0 = __half22float2(*reinterpret_cast<__half2*>(&u.x));
                float2 p1 = __half22float2(*reinterpret_cast<__half2*>(&u.y));
                float2 p2 = __half22float2(*reinterpret_cast<__half2*>(&u.z));
                float2 p3 = __half22float2(*reinterpret_cast<__half2*>(&u.w));
                acc[8 * i + 0] += p0.x; acc[8 * i + 1] += p0.y;
                acc[8 * i + 2] += p1.x; acc[8 * i + 3] += p1.y;
                acc[8 * i + 4] += p2.x; acc[8 * i + 5] += p2.y;
                acc[8 * i + 6] += p3.x; acc[8 * i + 7] += p3.y;
            }
        }
        int d = s1 - s0;
        float inv = 1.0f / (float)(d > 0 ? d : 1);
        uint4* dst = (uint4*)(smem + SM_A + row * LROW + 256 + h * 128);
#pragma unroll
        for (int i = 0; i < 8; i++) {
            dst[i] = make_uint4(packh(acc[8 * i + 0] * inv, acc[8 * i + 1] * inv),
                                packh(acc[8 * i + 2] * inv, acc[8 * i + 3] * inv),
                                packh(acc[8 * i + 4] * inv, acc[8 * i + 5] * inv),
                                packh(acc[8 * i + 6] * inv, acc[8 * i + 7] * inv));
        }
    }
    CP_WAIT0();
    __syncthreads();

    // ---- mma.sync loop: warp tile 32x64 (4x2 warp grid), 16 k-steps -----------
    int wm = wid & 3, wn = wid >> 2;
    int row0 = wm * 32, col0 = wn * 64;

    float fc[2][8][4];
#pragma unroll
    for (int mi = 0; mi < 2; mi++)
#pragma unroll
        for (int ni = 0; ni < 8; ni++)
#pragma unroll
            for (int c = 0; c < 4; c++) fc[mi][ni][c] = 0.f;

    uint32_t sa = sb + SM_A, sbb = sb + SM_B;
#pragma unroll
    for (int kk = 0; kk < 16; kk++) {
        uint32_t a[2][4];
#pragma unroll
        for (int mi = 0; mi < 2; mi++) {
            uint32_t addr = sa + (row0 + mi * 16 + (lane & 15)) * LROW
                               + (kk * 16 + ((lane >> 4) << 3)) * 2;
            LDMATRIX_X4(a[mi][0], a[mi][1], a[mi][2], a[mi][3], addr);
        }
        uint32_t bt[8][2];
#pragma unroll
        for (int bj = 0; bj < 4; bj++) {
            int g = lane >> 3;
            uint32_t addr = sbb + (col0 + bj * 16 + ((g >> 1) << 3) + (lane & 7)) * LROW
                                + (kk * 16 + ((g & 1) << 3)) * 2;
            uint32_t r0, r1, r2, r3;
            LDMATRIX_X4(r0, r1, r2, r3, addr);
            bt[2 * bj][0] = r0; bt[2 * bj][1] = r1;
            bt[2 * bj + 1][0] = r2; bt[2 * bj + 1][1] = r3;
        }
#pragma unroll
        for (int mi = 0; mi < 2; mi++)
#pragma unroll
            for (int ni = 0; ni < 8; ni++)
                MMA16816(fc[mi][ni], a[mi], bt[ni]);
    }

    // ---- register-direct epilogue: bias + LN + ReLU ---------------------------
    // lane layout: rows row0+mi*16+{tr, tr+8}, cols col0+ni*8+2*tq+{0,1}
    int tq = lane & 3, tr = lane >> 2;
    float2 bv[8], gv[8], btv[8];
#pragma unroll
    for (int ni = 0; ni < 8; ni++) {
        int col = col0 + ni * 8 + 2 * tq;
        bv[ni] = *(const float2*)((const float*)(smem + SM_BIAS) + col);
        gv[ni] = *(const float2*)((const float*)(smem + SM_GAMMA) + col);
        btv[ni] = *(const float2*)((const float*)(smem + SM_BETA) + col);
    }
#pragma unroll
    for (int mi = 0; mi < 2; mi++)
#pragma unroll
        for (int ni = 0; ni < 8; ni++) {
            fc[mi][ni][0] += bv[ni].x; fc[mi][ni][1] += bv[ni].y;
            fc[mi][ni][2] += bv[ni].x; fc[mi][ni][3] += bv[ni].y;
        }

    float2* part = (float2*)(smem + SM_P);   // part[row][wn] : row*2 + wn
#pragma unroll
    for (int mi = 0; mi < 2; mi++) {
        float sA = 0.f, ssA = 0.f, sB = 0.f, ssB = 0.f;
#pragma unroll
        for (int ni = 0; ni < 8; ni++) {
            sA += fc[mi][ni][0] + fc[mi][ni][1];
            ssA += fc[mi][ni][0] * fc[mi][ni][0] + fc[mi][ni][1] * fc[mi][ni][1];
            sB += fc[mi][ni][2] + fc[mi][ni][3];
            ssB += fc[mi][ni][2] * fc[mi][ni][2] + fc[mi][ni][3] * fc[mi][ni][3];
        }
        sA += __shfl_xor_sync(0xFFFFFFFFu, sA, 1);  ssA += __shfl_xor_sync(0xFFFFFFFFu, ssA, 1);
        sA += __shfl_xor_sync(0xFFFFFFFFu, sA, 2);  ssA += __shfl_xor_sync(0xFFFFFFFFu, ssA, 2);
        sB += __shfl_xor_sync(0xFFFFFFFFu, sB, 1);  ssB += __shfl_xor_sync(0xFFFFFFFFu, ssB, 1);
        sB += __shfl_xor_sync(0xFFFFFFFFu, sB, 2);  ssB += __shfl_xor_sync(0xFFFFFFFFu, ssB, 2);
        if (tq == 0) {
            int rA = row0 + mi * 16 + tr;
            part[rA * 2 + wn] = make_float2(sA, ssA);
            part[(rA + 8) * 2 + wn] = make_float2(sB, ssB);
        }
    }
    __syncthreads();

#pragma unroll
    for (int mi = 0; mi < 2; mi++) {
        int rA = row0 + mi * 16 + tr;
        int rB = rA + 8;
        float2 pa0 = part[rA * 2 + 0], pa1 = part[rA * 2 + 1];
        float2 pb0 = part[rB * 2 + 0], pb1 = part[rB * 2 + 1];
        float sA = pa0.x + pa1.x, ssA = pa0.y + pa1.y;
        float sB = pb0.x + pb1.x, ssB = pb0.y + pb1.y;
        float meanA = sA * (1.0f / DD);
        float rstdA = rsqrtf(ssA * (1.0f / DD) - meanA * meanA + LN_EPS);
        float meanB = sB * (1.0f / DD);
        float rstdB = rsqrtf(ssB * (1.0f / DD) - meanB * meanB + LN_EPS);
        float* oA = out + (g0 + rA) * DD;
        float* oB = out + (g0 + rB) * DD;
#pragma unroll
        for (int ni = 0; ni < 8; ni++) {
            int col = col0 + ni * 8 + 2 * tq;
            float v0 = (fc[mi][ni][0] - meanA) * rstdA * gv[ni].x + btv[ni].x;
            float v1 = (fc[mi][ni][1] - meanA) * rstdA * gv[ni].y + btv[ni].y;
            float v2 = (fc[mi][ni][2] - meanB) * rstdB * gv[ni].x + btv[ni].x;
            float v3 = (fc[mi][ni][3] - meanB) * rstdB * gv[ni].y + btv[ni].y;
            *(float2*)(oA + col) = make_float2(v0 > 0.f ? v0 : 0.f, v1 > 0.f ? v1 : 0.f);
            *(float2*)(oB + col) = make_float2(v2 > 0.f ? v2 : 0.f, v3 > 0.f ? v3 : 0.f);
        }
    }
}

// ================= launch ======================================================
extern "C" void kernel_launch(void* const* d_in, const int* in_sizes, int n_in,
                              void* d_out, int out_size) {
    const float* x = nullptr;
    const int* edge = nullptr;
    const float* Wself = nullptr;
    const float* Wneigh = nullptr;
    const float* bias = nullptr;
    const float* gamma = nullptr;
    const float* beta = nullptr;
    int nW = 0, nV = 0;
    for (int i = 0; i < n_in; i++) {
        int s = in_sizes[i];
        if (s == NODES * DD) {
            if (!x) x = (const float*)d_in[i];
        } else if (s == 2 * EE || s == 4 * EE) {
            edge = (const int*)d_in[i];
        } else if (s == DD * DD) {
            if (nW == 0) Wself = (const float*)d_in[i];
            else if (nW == 1) Wneigh = (const float*)d_in[i];
            nW++;
        } else if (s == DD) {
            if (nV == 0) bias = (const float*)d_in[i];
            else if (nV == 1) gamma = (const float*)d_in[i];
            else if (nV == 2) beta = (const float*)d_in[i];
            nV++;
        }
    }

    cudaFuncSetAttribute(k_mm, cudaFuncAttributeMaxDynamicSharedMemorySize, SMEM_TOTAL);

    k_init<<<EE / 256, 256>>>(edge, Wself, Wneigh);
    k_count_xh<<<NODES * 16 / 256, 256>>>(edge, x);
    k_scan<<<1, 1024>>>();
    k_fill<<<EE / 256, 256>>>(edge);
    k_mm<<<NODES / ROWS, 256, SMEM_TOTAL>>>(bias, gamma, beta, (float*)d_out);
}

// round 15
// speedup vs baseline: 1.2805x; 1.2805x over previous
#include <cuda_runtime.h>
#include <cuda_fp16.h>
#include <cstdint>

// Problem constants (fixed by the dataset)
#define BB 16
#define NN 16384
#define DD 128
#define EE 65536
#define NODES (BB * NN)          // 262144
#define LN_EPS 1e-5f

// ================= scratch (__device__ globals) ================================
__device__ int g_is32;
__device__ __align__(16) int g_deg[NN];
__device__ __align__(16) int g_rowptr[NN + 1];
__device__ __align__(16) int g_cursor[NN];
__device__ int g_csr[EE];
__device__ uint4 g_xh[(size_t)NODES * 16];    // x as fp16 rows (256B each) = 64MB
__device__ uint4 g_w4[4096];                  // [128 n][256 k] fp16: Ws|Wn concat

__device__ __forceinline__ int clampN(int v) {
    return v < 0 ? 0 : (v >= NN ? NN - 1 : v);
}
__device__ __forceinline__ int edge_src(const int* e32, int e) {
    return clampN(g_is32 ? e32[e] : e32[2 * e]);
}
__device__ __forceinline__ int edge_dst(const int* e32, int e) {
    return clampN(g_is32 ? e32[EE + e] : e32[2 * EE + 2 * e]);
}
__device__ __forceinline__ uint32_t packh(float a, float b) {
    __half2 t(__float2half_rn(a), __float2half_rn(b));
    return *reinterpret_cast<uint32_t*>(&t);
}
__device__ __forceinline__ uint32_t smem_u32(const void* p) {
    uint32_t a;
    asm("{ .reg .u64 t; cvta.to.shared.u64 t, %1; cvt.u32.u64 %0, t; }" : "=r"(a) : "l"(p));
    return a;
}
#define CP_ASYNC16(sa, gp) \
    asm volatile("cp.async.cg.shared.global [%0], [%1], 16;" :: "r"(sa), "l"(gp))
#define CP_COMMIT() asm volatile("cp.async.commit_group;" ::: "memory")
#define CP_WAIT0()  asm volatile("cp.async.wait_group 0;" ::: "memory")
#define LDMATRIX_X4(r0, r1, r2, r3, a) \
    asm volatile("ldmatrix.sync.aligned.m8n8.x4.shared.b16 {%0,%1,%2,%3}, [%4];" \
                 : "=r"(r0), "=r"(r1), "=r"(r2), "=r"(r3) : "r"(a))
#define MMA16816(c, a, b) \
    asm volatile("mma.sync.aligned.m16n8k16.row.col.f32.f16.f16.f32 " \
                 "{%0,%1,%2,%3}, {%4,%5,%6,%7}, {%8,%9}, {%0,%1,%2,%3};" \
                 : "+f"((c)[0]), "+f"((c)[1]), "+f"((c)[2]), "+f"((c)[3]) \
                 : "r"((a)[0]), "r"((a)[1]), "r"((a)[2]), "r"((a)[3]), \
                   "r"((b)[0]), "r"((b)[1]))

// ================= fused init: zero degrees + dtype detect + weight convert ====
__global__ void k_init(const int* __restrict__ e32,
                       const float* __restrict__ Ws, const float* __restrict__ Wn) {
    int i = blockIdx.x * blockDim.x + threadIdx.x;
    if (i == 0) g_is32 = 0;
    if (i < NN) g_deg[i] = 0;
    if (i < EE && e32[2 * i + 1] != 0) g_is32 = 1;
    if (i < DD * DD) {
        __half* w = (__half*)g_w4;
        int n = i >> 7, k = i & 127;
        w[n * 256 + k] = __float2half_rn(Ws[i]);
        w[n * 256 + 128 + k] = __float2half_rn(Wn[i]);
    }
}

// ================= fused: degree count + x -> fp16 conversion ==================
__global__ void k_count_xh(const int* __restrict__ e32, const float* __restrict__ x) {
    size_t i = (size_t)blockIdx.x * blockDim.x + threadIdx.x;
    if (i < EE) atomicAdd(&g_deg[edge_dst(e32, (int)i)], 1);
    const float4* s = (const float4*)x + 2 * i;
    float4 a = s[0], b = s[1];
    g_xh[i] = make_uint4(packh(a.x, a.y), packh(a.z, a.w),
                         packh(b.x, b.y), packh(b.z, b.w));
}

// vectorized single-block scan: 1024 threads x 16 elems, warp shuffles
__global__ void k_scan() {
    __shared__ int wsum[32], wpre[32];
    int t = threadIdx.x, lane = t & 31, w = t >> 5;
    const int4* dg = (const int4*)g_deg;
    int loc[16];
#pragma unroll
    for (int q = 0; q < 4; q++) {
        int4 v = dg[t * 4 + q];
        loc[4 * q + 0] = v.x; loc[4 * q + 1] = v.y;
        loc[4 * q + 2] = v.z; loc[4 * q + 3] = v.w;
    }
    int s = 0;
#pragma unroll
    for (int m = 0; m < 16; m++) s += loc[m];
    int inc = s;
#pragma unroll
    for (int o = 1; o < 32; o <<= 1) {
        int u = __shfl_up_sync(0xFFFFFFFFu, inc, o);
        if (lane >= o) inc += u;
    }
    if (lane == 31) wsum[w] = inc;
    __syncthreads();
    if (w == 0) {
        int a = wsum[lane], ai = a;
#pragma unroll
        for (int o = 1; o < 32; o <<= 1) {
            int u = __shfl_up_sync(0xFFFFFFFFu, ai, o);
            if (lane >= o) ai += u;
        }
        wpre[lane] = ai - a;
    }
    __syncthreads();
    int run = wpre[w] + (inc - s);
    int rp[16];
#pragma unroll
    for (int m = 0; m < 16; m++) { rp[m] = run; run += loc[m]; }
    int4* rpo = (int4*)g_rowptr;
    int4* cu = (int4*)g_cursor;
#pragma unroll
    for (int q = 0; q < 4; q++) {
        int4 o4 = make_int4(rp[4 * q], rp[4 * q + 1], rp[4 * q + 2], rp[4 * q + 3]);
        rpo[t * 4 + q] = o4;
        cu[t * 4 + q] = o4;
    }
    if (t == 1023) g_rowptr[NN] = run;
}

__global__ void k_fill(const int* __restrict__ e32) {
    int e = blockIdx.x * blockDim.x + threadIdx.x;
    if (e < EE) {
        int d = edge_dst(e32, e);
        int pos = atomicAdd(&g_cursor[d], 1);
        if (pos >= 0 && pos < EE) g_csr[pos] = edge_src(e32, e);
    }
}

// ========== persistent fused: gather + mma.sync GEMM + bias + LN + ReLU ========
// 296 persistent CTAs (2/SM), each loops over 64-row tiles with stride gridDim.
// B ([Ws|Wn], 68KB) staged ONCE per CTA; per tile: cp.async x + gather -> MMA ->
// register-direct epilogue. CTA = 64 rows x 128 cols, 256 threads, 8 warps.
#define LDAB 264                              // fp16 per row (256 + 8 pad)
#define LROW (LDAB * 2)                       // 528 bytes per row
#define ROWS 64
#define NTILES (NODES / ROWS)                 // 4096
#define ABYTES (ROWS * LROW)                  // 33792
#define BBYTES (128 * LROW)                   // 67584
#define SM_BIAS  0
#define SM_GAMMA 512
#define SM_BETA  1024
#define SM_A     2048
#define SM_B     (SM_A + ABYTES)
#define SM_P     (SM_B + BBYTES)              // float2 part[64][4] = 2048
#define SMEM_TOTAL (SM_P + 2048)              // 105472 -> 2 CTAs/SM
#define PGRID 296                             // 2 x 148 SMs

__global__ void __launch_bounds__(256, 2)
k_mm(const float* __restrict__ bias,
     const float* __restrict__ gamma,
     const float* __restrict__ beta,
     float* __restrict__ out) {
    extern __shared__ char smem[];
    uint32_t sb = smem_u32(smem);
    int tid = threadIdx.x;
    int wid = tid >> 5, lane = tid & 31;

    if (tid < DD) {
        ((float*)(smem + SM_BIAS))[tid] = bias[tid];
        ((float*)(smem + SM_GAMMA))[tid] = gamma[tid];
        ((float*)(smem + SM_BETA))[tid] = beta[tid];
    }

    // ---- stage B once per persistent CTA --------------------------------------
#pragma unroll
    for (int i = 0; i < 16; i++) {
        int idx = tid + 256 * i;            // 0..4095 (128 rows x 32 chunks)
        int r = idx >> 5, c = idx & 31;
        CP_ASYNC16(sb + SM_B + r * LROW + c * 16, (const void*)(g_w4 + idx));
    }
    CP_COMMIT();

    int row = tid >> 2;           // 0..63
    int q = tid & 3;              // quarter of a row
    int wm = wid & 1, wn = wid >> 1;        // 2x4 warp grid
    int row0 = wm * 32, col0 = wn * 32;
    int tq = lane & 3, tr = lane >> 2;
    uint32_t sa = sb + SM_A, sbb = sb + SM_B;
    float2* part = (float2*)(smem + SM_P);   // part[row][wn] : row*4 + wn

    for (int tile = blockIdx.x; tile < NTILES; tile += PGRID) {
        size_t g0 = (size_t)tile * ROWS;

        // ---- cp.async x rows (A cols 0..127), overlapped with gather ----------
#pragma unroll
        for (int i = 0; i < 4; i++) {
            int idx = tid + 256 * i;        // 0..1023 (64 rows x 16 chunks)
            int r = idx >> 4, c = idx & 15;
            CP_ASYNC16(sb + SM_A + r * LROW + c * 16,
                       (const void*)(g_xh + (g0 + r) * 16 + c));
        }
        CP_COMMIT();

        // ---- gather neighbor mean (A cols 128..255) ---------------------------
        {
            int b = tile >> 8;              // 256 tiles per batch
            int n = ((tile & 255) << 6) + row;
            int s0 = g_rowptr[n];
            int s1 = g_rowptr[n + 1];
            const uint4* xb = g_xh + (size_t)b * NN * 16 + q * 4;
            float acc[32];
#pragma unroll
            for (int i = 0; i < 32; i++) acc[i] = 0.f;
            for (int e = s0; e < s1; e++) {
                const uint4* p = xb + (size_t)g_csr[e] * 16;
#pragma unroll
                for (int i = 0; i < 4; i++) {
                    uint4 u = p[i];
                    float2 p0 = __half22float2(*reinterpret_cast<__half2*>(&u.x));
                    float2 p1 = __half22float2(*reinterpret_cast<__half2*>(&u.y));
                    float2 p2 = __half22float2(*reinterpret_cast<__half2*>(&u.z));
                    float2 p3 = __half22float2(*reinterpret_cast<__half2*>(&u.w));
                    acc[8 * i + 0] += p0.x; acc[8 * i + 1] += p0.y;
                    acc[8 * i + 2] += p1.x; acc[8 * i + 3] += p1.y;
                    acc[8 * i + 4] += p2.x; acc[8 * i + 5] += p2.y;
                    acc[8 * i + 6] += p3.x; acc[8 * i + 7] += p3.y;
                }
            }
            int d = s1 - s0;
            float inv = 1.0f / (float)(d > 0 ? d : 1);
            uint4* dst = (uint4*)(smem + SM_A + row * LROW + 256 + q * 64);
#pragma unroll
            for (int i = 0; i < 4; i++) {
                dst[i] = make_uint4(packh(acc[8 * i + 0] * inv, acc[8 * i + 1] * inv),
                                    packh(acc[8 * i + 2] * inv, acc[8 * i + 3] * inv),
                                    packh(acc[8 * i + 4] * inv, acc[8 * i + 5] * inv),
                                    packh(acc[8 * i + 6] * inv, acc[8 * i + 7] * inv));
            }
        }
        CP_WAIT0();
        __syncthreads();

        // ---- mma.sync loop: warp tile 32x32, 16 k-steps -----------------------
        float fc[2][4][4];
#pragma unroll
        for (int mi = 0; mi < 2; mi++)
#pragma unroll
            for (int ni = 0; ni < 4; ni++)
#pragma unroll
                for (int c = 0; c < 4; c++) fc[mi][ni][c] = 0.f;

#pragma unroll
        for (int kk = 0; kk < 16; kk++) {
            uint32_t a[2][4];
#pragma unroll
            for (int mi = 0; mi < 2; mi++) {
                uint32_t addr = sa + (row0 + mi * 16 + (lane & 15)) * LROW
                                   + (kk * 16 + ((lane >> 4) << 3)) * 2;
                LDMATRIX_X4(a[mi][0], a[mi][1], a[mi][2], a[mi][3], addr);
            }
            uint32_t bt[4][2];
#pragma unroll
            for (int bj = 0; bj < 2; bj++) {
                int g = lane >> 3;
                uint32_t addr = sbb + (col0 + bj * 16 + ((g >> 1) << 3) + (lane & 7)) * LROW
                                    + (kk * 16 + ((g & 1) << 3)) * 2;
                uint32_t r0, r1, r2, r3;
                LDMATRIX_X4(r0, r1, r2, r3, addr);
                bt[2 * bj][0] = r0; bt[2 * bj][1] = r1;
                bt[2 * bj + 1][0] = r2; bt[2 * bj + 1][1] = r3;
            }
#pragma unroll
            for (int mi = 0; mi < 2; mi++)
#pragma unroll
                for (int ni = 0; ni < 4; ni++)
                    MMA16816(fc[mi][ni], a[mi], bt[ni]);
        }

        // ---- register-direct epilogue: bias + LN + ReLU -----------------------
        float2 bv[4], gv[4], btv[4];
#pragma unroll
        for (int ni = 0; ni < 4; ni++) {
            int col = col0 + ni * 8 + 2 * tq;
            bv[ni] = *(const float2*)((const float*)(smem + SM_BIAS) + col);
            gv[ni] = *(const float2*)((const float*)(smem + SM_GAMMA) + col);
            btv[ni] = *(const float2*)((const float*)(smem + SM_BETA) + col);
        }
#pragma unroll
        for (int mi = 0; mi < 2; mi++)
#pragma unroll
            for (int ni = 0; ni < 4; ni++) {
                fc[mi][ni][0] += bv[ni].x; fc[mi][ni][1] += bv[ni].y;
                fc[mi][ni][2] += bv[ni].x; fc[mi][ni][3] += bv[ni].y;
            }

#pragma unroll
        for (int mi = 0; mi < 2; mi++) {
            float sA = 0.f, ssA = 0.f, sB = 0.f, ssB = 0.f;
#pragma unroll
            for (int ni = 0; ni < 4; ni++) {
                sA += fc[mi][ni][0] + fc[mi][ni][1];
                ssA += fc[mi][ni][0] * fc[mi][ni][0] + fc[mi][ni][1] * fc[mi][ni][1];
                sB += fc[mi][ni][2] + fc[mi][ni][3];
                ssB += fc[mi][ni][2] * fc[mi][ni][2] + fc[mi][ni][3] * fc[mi][ni][3];
            }
            sA += __shfl_xor_sync(0xFFFFFFFFu, sA, 1);  ssA += __shfl_xor_sync(0xFFFFFFFFu, ssA, 1);
            sA += __shfl_xor_sync(0xFFFFFFFFu, sA, 2);  ssA += __shfl_xor_sync(0xFFFFFFFFu, ssA, 2);
            sB += __shfl_xor_sync(0xFFFFFFFFu, sB, 1);  ssB += __shfl_xor_sync(0xFFFFFFFFu, ssB, 1);
            sB += __shfl_xor_sync(0xFFFFFFFFu, sB, 2);  ssB += __shfl_xor_sync(0xFFFFFFFFu, ssB, 2);
            if (tq == 0) {
                int rA = row0 + mi * 16 + tr;
                part[rA * 4 + wn] = make_float2(sA, ssA);
                part[(rA + 8) * 4 + wn] = make_float2(sB, ssB);
            }
        }
        __syncthreads();

#pragma unroll
        for (int mi = 0; mi < 2; mi++) {
            int rA = row0 + mi * 16 + tr;
            int rB = rA + 8;
            float2 pa0 = part[rA * 4 + 0], pa1 = part[rA * 4 + 1];
            float2 pa2 = part[rA * 4 + 2], pa3 = part[rA * 4 + 3];
            float2 pb0 = part[rB * 4 + 0], pb1 = part[rB * 4 + 1];
            float2 pb2 = part[rB * 4 + 2], pb3 = part[rB * 4 + 3];
            float sA = pa0.x + pa1.x + pa2.x + pa3.x;
            float ssA = pa0.y + pa1.y + pa2.y + pa3.y;
            float sB = pb0.x + pb1.x + pb2.x + pb3.x;
            float ssB = pb0.y + pb1.y + pb2.y + pb3.y;
            float meanA = sA * (1.0f / DD);
            float rstdA = rsqrtf(ssA * (1.0f / DD) - meanA * meanA + LN_EPS);
            float meanB = sB * (1.0f / DD);
            float rstdB = rsqrtf(ssB * (1.0f / DD) - meanB * meanB + LN_EPS);
            float* oA = out + (g0 + rA) * DD;
            float* oB = out + (g0 + rB) * DD;
#pragma unroll
            for (int ni = 0; ni < 4; ni++) {
                int col = col0 + ni * 8 + 2 * tq;
                float v0 = (fc[mi][ni][0] - meanA) * rstdA * gv[ni].x + btv[ni].x;
                float v1 = (fc[mi][ni][1] - meanA) * rstdA * gv[ni].y + btv[ni].y;
                float v2 = (fc[mi][ni][2] - meanB) * rstdB * gv[ni].x + btv[ni].x;
                float v3 = (fc[mi][ni][3] - meanB) * rstdB * gv[ni].y + btv[ni].y;
                *(float2*)(oA + col) = make_float2(v0 > 0.f ? v0 : 0.f, v1 > 0.f ? v1 : 0.f);
                *(float2*)(oB + col) = make_float2(v2 > 0.f ? v2 : 0.f, v3 > 0.f ? v3 : 0.f);
            }
        }
        __syncthreads();   // A/part reuse safe before next tile
    }
}

// ================= launch ======================================================
extern "C" void kernel_launch(void* const* d_in, const int* in_sizes, int n_in,
                              void* d_out, int out_size) {
    const float* x = nullptr;
    const int* edge = nullptr;
    const float* Wself = nullptr;
    const float* Wneigh = nullptr;
    const float* bias = nullptr;
    const float* gamma = nullptr;
    const float* beta = nullptr;
    int nW = 0, nV = 0;
    for (int i = 0; i < n_in; i++) {
        int s = in_sizes[i];
        if (s == NODES * DD) {
            if (!x) x = (const float*)d_in[i];
        } else if (s == 2 * EE || s == 4 * EE) {
            edge = (const int*)d_in[i];
        } else if (s == DD * DD) {
            if (nW == 0) Wself = (const float*)d_in[i];
            else if (nW == 1) Wneigh = (const float*)d_in[i];
            nW++;
        } else if (s == DD) {
            if (nV == 0) bias = (const float*)d_in[i];
            else if (nV == 1) gamma = (const float*)d_in[i];
            else if (nV == 2) beta = (const float*)d_in[i];
            nV++;
        }
    }

    cudaFuncSetAttribute(k_mm, cudaFuncAttributeMaxDynamicSharedMemorySize, SMEM_TOTAL);

    k_init<<<EE / 256, 256>>>(edge, Wself, Wneigh);
    k_count_xh<<<NODES * 16 / 256, 256>>>(edge, x);
    k_scan<<<1, 1024>>>();
    k_fill<<<EE / 256, 256>>>(edge);
    k_mm<<<PGRID, 256, SMEM_TOTAL>>>(bias, gamma, beta, (float*)d_out);
}